// round 2
// baseline (speedup 1.0000x reference)
#include <cuda_runtime.h>
#include <cuda_bf16.h>
#include <math_constants.h>

// Problem constants (fixed by the reference):
//   x:  [N, D] fp32,  cb: [K, D] fp32 (L2-normalized rows)
//   sims = x @ cb^T  [N, K];  labels = argmax_k sims (first occurrence); preds = cb[labels]
#define NN 131072
#define DD 512
#define KK 2048

#define BM 128
#define BN 128
#define BK 16

// ---------------------------------------------------------------------------
// Kernel 1: fp32 SGEMM (NT): C[n,k] = sum_d A[n,d] * B[k,d]
// 128x128 block tile, BK=16, 256 threads, 8x8 per-thread microtile.
// ---------------------------------------------------------------------------
__global__ __launch_bounds__(256, 2)
void sgemm_nt_kernel(const float* __restrict__ A,
                     const float* __restrict__ B,
                     float* __restrict__ C)
{
    __shared__ float As[BK][BM + 4];
    __shared__ float Bs[BK][BN + 4];

    const int tid = threadIdx.x;
    const int bm = blockIdx.y * BM;
    const int bn = blockIdx.x * BN;

    // Global-load mapping: 512 float4 per operand per tile, 2 per thread.
    const int lrow = tid >> 2;          // 0..63  (second load covers +64)
    const int lc4  = (tid & 3) * 4;     // 0,4,8,12 within BK

    const float* Aptr = A + (size_t)(bm + lrow) * DD + lc4;
    const float* Bptr = B + (size_t)(bn + lrow) * DD + lc4;

    // Compute mapping: 16x16 thread grid, each owns rows {rb..rb+3, rb+64..}, cols likewise.
    const int rowBase = (tid >> 4) * 4;   // 0..60
    const int colBase = (tid & 15) * 4;   // 0..60

    float acc[8][8];
#pragma unroll
    for (int i = 0; i < 8; ++i)
#pragma unroll
        for (int j = 0; j < 8; ++j) acc[i][j] = 0.0f;

    // Prefetch tile 0 into registers
    float4 pa0 = *(const float4*)(Aptr);
    float4 pa1 = *(const float4*)(Aptr + (size_t)64 * DD);
    float4 pb0 = *(const float4*)(Bptr);
    float4 pb1 = *(const float4*)(Bptr + (size_t)64 * DD);

    for (int kk = 0; kk < DD; kk += BK) {
        // Store prefetched tile into smem (transposed)
        As[lc4 + 0][lrow] = pa0.x;  As[lc4 + 1][lrow] = pa0.y;
        As[lc4 + 2][lrow] = pa0.z;  As[lc4 + 3][lrow] = pa0.w;
        As[lc4 + 0][lrow + 64] = pa1.x;  As[lc4 + 1][lrow + 64] = pa1.y;
        As[lc4 + 2][lrow + 64] = pa1.z;  As[lc4 + 3][lrow + 64] = pa1.w;
        Bs[lc4 + 0][lrow] = pb0.x;  Bs[lc4 + 1][lrow] = pb0.y;
        Bs[lc4 + 2][lrow] = pb0.z;  Bs[lc4 + 3][lrow] = pb0.w;
        Bs[lc4 + 0][lrow + 64] = pb1.x;  Bs[lc4 + 1][lrow + 64] = pb1.y;
        Bs[lc4 + 2][lrow + 64] = pb1.z;  Bs[lc4 + 3][lrow + 64] = pb1.w;
        __syncthreads();

        // Prefetch next tile (overlaps with compute below)
        if (kk + BK < DD) {
            Aptr += BK; Bptr += BK;
            pa0 = *(const float4*)(Aptr);
            pa1 = *(const float4*)(Aptr + (size_t)64 * DD);
            pb0 = *(const float4*)(Bptr);
            pb1 = *(const float4*)(Bptr + (size_t)64 * DD);
        }

#pragma unroll
        for (int p = 0; p < BK; ++p) {
            float4 ra0 = *(const float4*)(&As[p][rowBase]);
            float4 ra1 = *(const float4*)(&As[p][rowBase + 64]);
            float4 rb0 = *(const float4*)(&Bs[p][colBase]);
            float4 rb1 = *(const float4*)(&Bs[p][colBase + 64]);
            float a[8] = {ra0.x, ra0.y, ra0.z, ra0.w, ra1.x, ra1.y, ra1.z, ra1.w};
            float b[8] = {rb0.x, rb0.y, rb0.z, rb0.w, rb1.x, rb1.y, rb1.z, rb1.w};
#pragma unroll
            for (int i = 0; i < 8; ++i)
#pragma unroll
                for (int j = 0; j < 8; ++j)
                    acc[i][j] = fmaf(a[i], b[j], acc[i][j]);
        }
        __syncthreads();
    }

    // Write back: rows {rowBase+i, rowBase+64+i}, cols {colBase.., colBase+64..}
#pragma unroll
    for (int i = 0; i < 8; ++i) {
        int r = bm + ((i < 4) ? (rowBase + i) : (rowBase + 64 + (i - 4)));
        float4 v0 = make_float4(acc[i][0], acc[i][1], acc[i][2], acc[i][3]);
        float4 v1 = make_float4(acc[i][4], acc[i][5], acc[i][6], acc[i][7]);
        float* crow = C + (size_t)r * KK + bn;
        *(float4*)(crow + colBase)      = v0;
        *(float4*)(crow + colBase + 64) = v1;
    }
}

// ---------------------------------------------------------------------------
// Kernel 2: per-row argmax (first-occurrence tie-break, matching jnp.argmax)
// fused with codebook gather (preds) and label store.
// One block (256 threads) per row.
// ---------------------------------------------------------------------------
__global__ __launch_bounds__(256)
void argmax_gather_kernel(const float* __restrict__ sims,
                          const float* __restrict__ cb,
                          float* __restrict__ preds,
                          void* __restrict__ labels,
                          int labels_are_i64)
{
    const int n = blockIdx.x;
    const int tid = threadIdx.x;
    const float4* row = (const float4*)(sims + (size_t)n * KK);

    float bv = -CUDART_INF_F;
    int   bi = 0;
#pragma unroll
    for (int it = 0; it < 2; ++it) {
        int j = tid + it * 256;          // increasing index order within thread
        float4 v = row[j];
        int base = j * 4;
        if (v.x > bv) { bv = v.x; bi = base; }
        if (v.y > bv) { bv = v.y; bi = base + 1; }
        if (v.z > bv) { bv = v.z; bi = base + 2; }
        if (v.w > bv) { bv = v.w; bi = base + 3; }
    }

    // Warp reduce (max value; on tie, min index)
#pragma unroll
    for (int off = 16; off > 0; off >>= 1) {
        float ov = __shfl_down_sync(0xFFFFFFFFu, bv, off);
        int   oi = __shfl_down_sync(0xFFFFFFFFu, bi, off);
        if (ov > bv || (ov == bv && oi < bi)) { bv = ov; bi = oi; }
    }

    __shared__ float sv[8];
    __shared__ int   si[8];
    __shared__ int   finalIdx;
    const int lane = tid & 31, warp = tid >> 5;
    if (lane == 0) { sv[warp] = bv; si[warp] = bi; }
    __syncthreads();
    if (tid == 0) {
        float fv = sv[0]; int fi = si[0];
#pragma unroll
        for (int w = 1; w < 8; ++w)
            if (sv[w] > fv || (sv[w] == fv && si[w] < fi)) { fv = sv[w]; fi = si[w]; }
        finalIdx = fi;
        if (labels_are_i64) ((long long*)labels)[n] = (long long)fi;
        else                ((float*)labels)[n] = (float)fi;
    }
    __syncthreads();

    const int lbl = finalIdx;
    // Gather preds row: 512 floats = 128 float4 (threads 0..127)
    if (tid < 128) {
        float4 c = ((const float4*)(cb + (size_t)lbl * DD))[tid];
        ((float4*)(preds + (size_t)n * DD))[tid] = c;
    }
}

// ---------------------------------------------------------------------------
// Launch
// ---------------------------------------------------------------------------
extern "C" void kernel_launch(void* const* d_in, const int* in_sizes, int n_in,
                              void* d_out, int out_size)
{
    const float* x  = (const float*)d_in[0];   // [N, D]
    const float* cb = (const float*)d_in[1];   // [K, D]

    float* out = (float*)d_out;
    const size_t predsSz = (size_t)NN * DD;        // 67,108,864
    const size_t simsSz  = (size_t)NN * KK;        // 268,435,456

    // Output layout: [preds | labels | sims]. Labels are int64 in the
    // reference; detect from out_size whether the label region holds raw
    // int64 (2 f32 slots per row) or f32-cast values (1 slot per row).
    size_t labelElems;
    int labels_are_i64;
    if ((size_t)(unsigned)out_size == predsSz + 2 * (size_t)NN + simsSz) {
        labelElems = 2 * (size_t)NN; labels_are_i64 = 1;
    } else {
        labelElems = (size_t)NN;     labels_are_i64 = 0;
    }

    float* preds  = out;
    void*  labels = (void*)(out + predsSz);
    float* sims   = out + predsSz + labelElems;

    dim3 grid(KK / BN, NN / BM);   // (16, 1024)
    sgemm_nt_kernel<<<grid, 256>>>(x, cb, sims);
    argmax_gather_kernel<<<NN, 256>>>(sims, cb, preds, labels, labels_are_i64);
}

// round 5
// speedup vs baseline: 1.4643x; 1.4643x over previous
#include <cuda_runtime.h>
#include <cuda_fp16.h>
#include <math_constants.h>
#include <cstdint>

// Problem constants:
//   x: [N, D] fp32,  cb: [K, D] fp32 (unit rows)
//   sims = x @ cb^T [N,K]; labels = argmax_k (first occurrence); preds = cb[labels]
#define NN 131072
#define DD 512
#define KK 2048

#define BM 128
#define BN 128
#define BK 32
#define NITERS (DD / BK)    // 16

// Fragment-layout smem (u32 words), per stage:
//   A: 2 k16 x 8 m16 x 4 regs x 32 lanes = 2048 words (hi), 2048 (lo)
//   B: 2 k16 x 16 n8 x 2 regs x 32 lanes = 2048 words (hi), 2048 (lo)
#define AH_OFF 0
#define AL_OFF 2048
#define BH_OFF 4096
#define BL_OFF 6144
#define STAGE_U32 8192
#define SMEM_BYTES (2 * STAGE_U32 * 4)   // 65536

__device__ __forceinline__ uint32_t h2u(half2 h) {
    return *reinterpret_cast<uint32_t*>(&h);
}

// fragment scatter index for A element (row in [0,128), kp = col/2 in [0,16))
__device__ __forceinline__ int a_idx(int row, int kp) {
    int k16 = kp >> 3, kpl = kp & 7;
    int m16 = row >> 4, rl = row & 15;
    int reg = (rl >> 3) + ((kpl >> 2) << 1);
    int lane = ((rl & 7) << 2) + (kpl & 3);
    return (((k16 << 3) + m16) * 4 + reg) * 32 + lane;
}
// fragment scatter index for B element (n in [0,128), kp in [0,16))
__device__ __forceinline__ int b_idx(int n, int kp) {
    int k16 = kp >> 3, kpl = kp & 7;
    int n8 = n >> 3, nl = n & 7;
    int reg = kpl >> 2;
    int lane = (nl << 2) + (kpl & 3);
    return (((k16 << 4) + n8) * 2 + reg) * 32 + lane;
}

__device__ __forceinline__ void mma16816(float* d, const uint32_t* a, const uint32_t* b) {
    asm volatile(
        "mma.sync.aligned.m16n8k16.row.col.f32.f16.f16.f32 "
        "{%0,%1,%2,%3}, {%4,%5,%6,%7}, {%8,%9}, {%0,%1,%2,%3};"
        : "+f"(d[0]), "+f"(d[1]), "+f"(d[2]), "+f"(d[3])
        : "r"(a[0]), "r"(a[1]), "r"(a[2]), "r"(a[3]), "r"(b[0]), "r"(b[1]));
}

// ---------------------------------------------------------------------------
// Kernel 1: fp16x3 GEMM  C[m,n] = sum_d A[m,d]*B[n,d]  (emulated fp32)
// ---------------------------------------------------------------------------
__global__ __launch_bounds__(256, 1)
void gemm_f16x3_kernel(const float* __restrict__ A,
                       const float* __restrict__ B,
                       float* __restrict__ C)
{
    extern __shared__ uint32_t dsm[];
    const int tid = threadIdx.x;
    const int lane = tid & 31;
    const int wid = tid >> 5;
    const int wm = wid & 1;          // 2 m-warps
    const int wn = wid >> 1;         // 4 n-warps
    const int bm = blockIdx.y * BM;
    const int bn = blockIdx.x * BN;

    // per-thread global-load coordinates (4 float4 per operand per tile)
    int rowA[4], f4A[4];
#pragma unroll
    for (int j = 0; j < 4; ++j) {
        int q = j * 256 + tid;
        rowA[j] = q >> 3;
        f4A[j] = q & 7;
    }

    float4 pa[4], pb[4];
    auto prefetch = [&](int it) {
        const int kk = it * BK;
#pragma unroll
        for (int j = 0; j < 4; ++j) {
            pa[j] = *(const float4*)(A + (size_t)(bm + rowA[j]) * DD + kk + f4A[j] * 4);
            pb[j] = *(const float4*)(B + (size_t)(bn + rowA[j]) * DD + kk + f4A[j] * 4);
        }
    };
    auto store_stage = [&](uint32_t* S) {
#pragma unroll
        for (int j = 0; j < 4; ++j) {
            // A
            {
                float4 v = pa[j];
                half2 h01 = __float22half2_rn(make_float2(v.x, v.y));
                half2 h23 = __float22half2_rn(make_float2(v.z, v.w));
                float2 f01 = __half22float2(h01), f23 = __half22float2(h23);
                half2 l01 = __float22half2_rn(make_float2(v.x - f01.x, v.y - f01.y));
                half2 l23 = __float22half2_rn(make_float2(v.z - f23.x, v.w - f23.y));
                int idx = a_idx(rowA[j], 2 * f4A[j]);
                *(uint2*)&S[AH_OFF + idx] = make_uint2(h2u(h01), h2u(h23));
                *(uint2*)&S[AL_OFF + idx] = make_uint2(h2u(l01), h2u(l23));
            }
            // B
            {
                float4 v = pb[j];
                half2 h01 = __float22half2_rn(make_float2(v.x, v.y));
                half2 h23 = __float22half2_rn(make_float2(v.z, v.w));
                float2 f01 = __half22float2(h01), f23 = __half22float2(h23);
                half2 l01 = __float22half2_rn(make_float2(v.x - f01.x, v.y - f01.y));
                half2 l23 = __float22half2_rn(make_float2(v.z - f23.x, v.w - f23.y));
                int idx = b_idx(rowA[j], 2 * f4A[j]);
                *(uint2*)&S[BH_OFF + idx] = make_uint2(h2u(h01), h2u(h23));
                *(uint2*)&S[BL_OFF + idx] = make_uint2(h2u(l01), h2u(l23));
            }
        }
    };

    float acc[4][4][4];
#pragma unroll
    for (int i = 0; i < 4; ++i)
#pragma unroll
        for (int j = 0; j < 4; ++j)
#pragma unroll
            for (int r = 0; r < 4; ++r) acc[i][j][r] = 0.0f;

    prefetch(0);
    store_stage(dsm);            // stage 0
    __syncthreads();

#pragma unroll 1
    for (int it = 0; it < NITERS; ++it) {
        uint32_t* S = dsm + (it & 1) * STAGE_U32;
        uint32_t* Snxt = dsm + ((it & 1) ^ 1) * STAGE_U32;

        if (it + 1 < NITERS) prefetch(it + 1);

#pragma unroll
        for (int s = 0; s < 2; ++s) {
            uint32_t ah[4][4], al[4][4], bh[4][2], bl[4][2];
#pragma unroll
            for (int i = 0; i < 4; ++i) {
                int base = ((s * 8 + wm * 4 + i) * 4) * 32 + lane;
#pragma unroll
                for (int r = 0; r < 4; ++r) {
                    ah[i][r] = S[AH_OFF + base + r * 32];
                    al[i][r] = S[AL_OFF + base + r * 32];
                }
            }
#pragma unroll
            for (int j = 0; j < 4; ++j) {
                int base = ((s * 16 + wn * 4 + j) * 2) * 32 + lane;
#pragma unroll
                for (int r = 0; r < 2; ++r) {
                    bh[j][r] = S[BH_OFF + base + r * 32];
                    bl[j][r] = S[BL_OFF + base + r * 32];
                }
            }
            // pass 1: hi*hi
#pragma unroll
            for (int i = 0; i < 4; ++i)
#pragma unroll
                for (int j = 0; j < 4; ++j) mma16816(acc[i][j], ah[i], bh[j]);
            // pass 2: hi*lo
#pragma unroll
            for (int i = 0; i < 4; ++i)
#pragma unroll
                for (int j = 0; j < 4; ++j) mma16816(acc[i][j], ah[i], bl[j]);
            // pass 3: lo*hi
#pragma unroll
            for (int i = 0; i < 4; ++i)
#pragma unroll
                for (int j = 0; j < 4; ++j) mma16816(acc[i][j], al[i], bh[j]);
        }

        if (it + 1 < NITERS) store_stage(Snxt);
        __syncthreads();
    }

    // epilogue: c-frag direct STG (adjacent col pairs -> float2)
#pragma unroll
    for (int i = 0; i < 4; ++i) {
        int r0 = bm + wm * 64 + i * 16 + (lane >> 2);
#pragma unroll
        for (int j = 0; j < 4; ++j) {
            int c = bn + wn * 32 + j * 8 + (lane & 3) * 2;
            *(float2*)&C[(size_t)r0 * KK + c] = make_float2(acc[i][j][0], acc[i][j][1]);
            *(float2*)&C[(size_t)(r0 + 8) * KK + c] = make_float2(acc[i][j][2], acc[i][j][3]);
        }
    }
}

// ---------------------------------------------------------------------------
// Kernel 2: per-row top-2 argmax + near-tie sequential-fp32 fixup + gather
// The fixup replicates the R1 FFMA kernel's arithmetic bitwise: a single
// d=0..511 sequential fmaf chain per candidate (that kernel matched the
// reference with rel_err 0.0, so its tie decisions are the ground truth).
// ---------------------------------------------------------------------------
__device__ __forceinline__ void merge2(float& v1, int& i1, float& v2, int& i2,
                                       float ov, int oi) {
    if (ov > v1 || (ov == v1 && oi < i1)) {
        v2 = v1; i2 = i1; v1 = ov; i1 = oi;
    } else if (ov > v2 || (ov == v2 && oi < i2)) {
        v2 = ov; i2 = oi;
    }
}

__global__ __launch_bounds__(256)
void argmax_gather_kernel(const float* __restrict__ sims,
                          const float* __restrict__ cb,
                          const float* __restrict__ x,
                          float* __restrict__ preds,
                          void* __restrict__ labels,
                          int labels_are_i64)
{
    const int n = blockIdx.x;
    const int tid = threadIdx.x;
    const float4* row = (const float4*)(sims + (size_t)n * KK);

    float v1 = -CUDART_INF_F, v2 = -CUDART_INF_F;
    int i1 = 0x7FFFFFFF, i2 = 0x7FFFFFFF;
#pragma unroll
    for (int it = 0; it < 2; ++it) {
        int j = tid + it * 256;
        float4 v = row[j];
        int base = j * 4;
        merge2(v1, i1, v2, i2, v.x, base);
        merge2(v1, i1, v2, i2, v.y, base + 1);
        merge2(v1, i1, v2, i2, v.z, base + 2);
        merge2(v1, i1, v2, i2, v.w, base + 3);
    }
#pragma unroll
    for (int off = 16; off > 0; off >>= 1) {
        float ov1 = __shfl_down_sync(0xFFFFFFFFu, v1, off);
        int   oi1 = __shfl_down_sync(0xFFFFFFFFu, i1, off);
        float ov2 = __shfl_down_sync(0xFFFFFFFFu, v2, off);
        int   oi2 = __shfl_down_sync(0xFFFFFFFFu, i2, off);
        merge2(v1, i1, v2, i2, ov1, oi1);
        merge2(v1, i1, v2, i2, ov2, oi2);
    }

    __shared__ float sv1[8], sv2[8];
    __shared__ int   si1[8], si2[8];
    __shared__ float s_exact[2];
    __shared__ int   s_i1, s_i2, s_final, s_fix;
    const int lane = tid & 31, warp = tid >> 5;
    if (lane == 0) { sv1[warp] = v1; si1[warp] = i1; sv2[warp] = v2; si2[warp] = i2; }
    __syncthreads();
    if (tid == 0) {
        float fv1 = sv1[0], fv2 = sv2[0];
        int fi1 = si1[0], fi2 = si2[0];
#pragma unroll
        for (int w = 1; w < 8; ++w) {
            merge2(fv1, fi1, fv2, fi2, sv1[w], si1[w]);
            merge2(fv1, fi1, fv2, fi2, sv2[w], si2[w]);
        }
        s_i1 = fi1; s_i2 = fi2; s_final = fi1;
        s_fix = (fv1 - fv2 < 1e-2f) ? 1 : 0;
    }
    __syncthreads();

    if (s_fix) {
        // Sequential fp32 fmaf chain per candidate — bitwise identical to the
        // exact-fp32 kernel's per-element accumulation order.
        if (tid < 2) {
            const int cand = (tid == 0) ? s_i1 : s_i2;
            const float* xr = x + (size_t)n * DD;
            const float* cr = cb + (size_t)cand * DD;
            float s = 0.0f;
#pragma unroll 8
            for (int d = 0; d < DD; ++d) s = fmaf(xr[d], cr[d], s);
            s_exact[tid] = s;
        }
        __syncthreads();
        if (tid == 0) {
            const float sA = s_exact[0], sB = s_exact[1];
            const int a = s_i1, b = s_i2;
            int fin;
            if (sA > sB)      fin = a;
            else if (sB > sA) fin = b;
            else              fin = (a < b) ? a : b;
            s_final = fin;
        }
        __syncthreads();
    }

    const int lbl = s_final;
    if (tid == 0) {
        if (labels_are_i64) ((long long*)labels)[n] = (long long)lbl;
        else                ((float*)labels)[n] = (float)lbl;
    }
    if (tid < 128) {
        float4 c = ((const float4*)(cb + (size_t)lbl * DD))[tid];
        ((float4*)(preds + (size_t)n * DD))[tid] = c;
    }
}

// ---------------------------------------------------------------------------
// Launch
// ---------------------------------------------------------------------------
extern "C" void kernel_launch(void* const* d_in, const int* in_sizes, int n_in,
                              void* d_out, int out_size)
{
    const float* x  = (const float*)d_in[0];   // [N, D]
    const float* cb = (const float*)d_in[1];   // [K, D]

    float* out = (float*)d_out;
    const size_t predsSz = (size_t)NN * DD;
    const size_t simsSz  = (size_t)NN * KK;

    size_t labelElems;
    int labels_are_i64;
    if ((size_t)(unsigned)out_size == predsSz + 2 * (size_t)NN + simsSz) {
        labelElems = 2 * (size_t)NN; labels_are_i64 = 1;
    } else {
        labelElems = (size_t)NN;     labels_are_i64 = 0;
    }

    float* preds  = out;
    void*  labels = (void*)(out + predsSz);
    float* sims   = out + predsSz + labelElems;

    static int attr_set = 0;
    if (!attr_set) {
        cudaFuncSetAttribute(gemm_f16x3_kernel,
                             cudaFuncAttributeMaxDynamicSharedMemorySize, SMEM_BYTES);
        attr_set = 1;
    }

    dim3 grid(KK / BN, NN / BM);   // (16, 1024)
    gemm_f16x3_kernel<<<grid, 256, SMEM_BYTES>>>(x, cb, sims);
    argmax_gather_kernel<<<NN, 256>>>(sims, cb, x, preds, labels, labels_are_i64);
}

// round 6
// speedup vs baseline: 1.7099x; 1.1677x over previous
#include <cuda_runtime.h>
#include <cuda_fp16.h>
#include <math_constants.h>
#include <cstdint>

// Problem constants:
//   x: [N, D] fp32,  cb: [K, D] fp32 (unit rows)
//   sims = x @ cb^T [N,K]; labels = argmax_k (first occurrence); preds = cb[labels]
#define NN 131072
#define DD 512
#define KK 2048

#define BM 128
#define BN 128
#define BK 32
#define NITERS (DD / BK)    // 16

// Fragment-layout smem (u32 words), per stage, CONSUMER-VECTORIZED:
//   A word: ((k16*8 + m16)*32 + lane)*4 + reg   -> uint4 load per fragment
//   B word: ((k16*16 + n8)*32 + lane)*2 + reg   -> uint2 load per fragment
#define AH_OFF 0
#define AL_OFF 2048
#define BH_OFF 4096
#define BL_OFF 6144
#define STAGE_U32 8192
#define SMEM_BYTES (2 * STAGE_U32 * 4)   // 65536

__device__ __forceinline__ uint32_t h2u(half2 h) {
    return *reinterpret_cast<uint32_t*>(&h);
}

// word index for A element (row in [0,128), kp = k/2 in [0,16))
__device__ __forceinline__ int a_widx(int row, int kp) {
    int k16 = kp >> 3, kpl = kp & 7;
    int m16 = row >> 4, rl = row & 15;
    int reg = (rl >> 3) + ((kpl >> 2) << 1);
    int lane = ((rl & 7) << 2) + (kpl & 3);
    return (((k16 << 3) + m16) * 32 + lane) * 4 + reg;
}
// word index for B element (n in [0,128), kp in [0,16))
__device__ __forceinline__ int b_widx(int n, int kp) {
    int k16 = kp >> 3, kpl = kp & 7;
    int n8 = n >> 3, nl = n & 7;
    int reg = kpl >> 2;
    int lane = (nl << 2) + (kpl & 3);
    return (((k16 << 4) + n8) * 32 + lane) * 2 + reg;
}

__device__ __forceinline__ void mma16816(float* d, const uint32_t* a, const uint32_t* b) {
    asm volatile(
        "mma.sync.aligned.m16n8k16.row.col.f32.f16.f16.f32 "
        "{%0,%1,%2,%3}, {%4,%5,%6,%7}, {%8,%9}, {%0,%1,%2,%3};"
        : "+f"(d[0]), "+f"(d[1]), "+f"(d[2]), "+f"(d[3])
        : "r"(a[0]), "r"(a[1]), "r"(a[2]), "r"(a[3]), "r"(b[0]), "r"(b[1]));
}

// ---------------------------------------------------------------------------
// Kernel 1: fp16x3 GEMM  C[m,n] = sum_d A[m,d]*B[n,d]  (emulated fp32)
// ---------------------------------------------------------------------------
__global__ __launch_bounds__(256, 1)
void gemm_f16x3_kernel(const float* __restrict__ A,
                       const float* __restrict__ B,
                       float* __restrict__ C)
{
    extern __shared__ uint32_t dsm[];
    const int tid = threadIdx.x;
    const int lane = tid & 31;
    const int wid = tid >> 5;
    const int wm = wid & 1;          // 2 m-warps
    const int wn = wid >> 1;         // 4 n-warps
    const int bm = blockIdx.y * BM;
    const int bn = blockIdx.x * BN;

    // per-thread global-load coordinates (4 float4 per operand per tile)
    int rowA[4], f4A[4];
#pragma unroll
    for (int j = 0; j < 4; ++j) {
        int q = j * 256 + tid;
        rowA[j] = q >> 3;
        f4A[j] = q & 7;
    }

    float4 pa[4], pb[4];
    auto prefetch = [&](int it) {
        const int kk = it * BK;
#pragma unroll
        for (int j = 0; j < 4; ++j) {
            pa[j] = *(const float4*)(A + (size_t)(bm + rowA[j]) * DD + kk + f4A[j] * 4);
            pb[j] = *(const float4*)(B + (size_t)(bn + rowA[j]) * DD + kk + f4A[j] * 4);
        }
    };
    auto store_stage = [&](uint32_t* S) {
#pragma unroll
        for (int j = 0; j < 4; ++j) {
            // A
            {
                float4 v = pa[j];
                half2 h01 = __float22half2_rn(make_float2(v.x, v.y));
                half2 h23 = __float22half2_rn(make_float2(v.z, v.w));
                float2 f01 = __half22float2(h01), f23 = __half22float2(h23);
                half2 l01 = __float22half2_rn(make_float2(v.x - f01.x, v.y - f01.y));
                half2 l23 = __float22half2_rn(make_float2(v.z - f23.x, v.w - f23.y));
                int i0 = a_widx(rowA[j], 2 * f4A[j]);   // kp and kp+1 -> i0, i0+4
                S[AH_OFF + i0]     = h2u(h01);
                S[AH_OFF + i0 + 4] = h2u(h23);
                S[AL_OFF + i0]     = h2u(l01);
                S[AL_OFF + i0 + 4] = h2u(l23);
            }
            // B
            {
                float4 v = pb[j];
                half2 h01 = __float22half2_rn(make_float2(v.x, v.y));
                half2 h23 = __float22half2_rn(make_float2(v.z, v.w));
                float2 f01 = __half22float2(h01), f23 = __half22float2(h23);
                half2 l01 = __float22half2_rn(make_float2(v.x - f01.x, v.y - f01.y));
                half2 l23 = __float22half2_rn(make_float2(v.z - f23.x, v.w - f23.y));
                int i0 = b_widx(rowA[j], 2 * f4A[j]);   // kp and kp+1 -> i0, i0+2
                S[BH_OFF + i0]     = h2u(h01);
                S[BH_OFF + i0 + 2] = h2u(h23);
                S[BL_OFF + i0]     = h2u(l01);
                S[BL_OFF + i0 + 2] = h2u(l23);
            }
        }
    };

    float acc[4][4][4];
#pragma unroll
    for (int i = 0; i < 4; ++i)
#pragma unroll
        for (int j = 0; j < 4; ++j)
#pragma unroll
            for (int r = 0; r < 4; ++r) acc[i][j][r] = 0.0f;

    prefetch(0);
    store_stage(dsm);            // stage 0
    __syncthreads();

#pragma unroll 1
    for (int it = 0; it < NITERS; ++it) {
        uint32_t* S = dsm + (it & 1) * STAGE_U32;
        uint32_t* Snxt = dsm + ((it & 1) ^ 1) * STAGE_U32;

        if (it + 1 < NITERS) prefetch(it + 1);

#pragma unroll
        for (int s = 0; s < 2; ++s) {
            uint32_t ah[4][4], al[4][4], bh[4][2], bl[4][2];
            // hi fragments (vectorized: uint4 for A, uint2 for B)
#pragma unroll
            for (int i = 0; i < 4; ++i)
                *(uint4*)ah[i] = *(const uint4*)&S[AH_OFF + ((s * 8 + wm * 4 + i) * 32 + lane) * 4];
#pragma unroll
            for (int j = 0; j < 4; ++j)
                *(uint2*)bh[j] = *(const uint2*)&S[BH_OFF + ((s * 16 + wn * 4 + j) * 32 + lane) * 2];
            // pass 1: hi*hi
#pragma unroll
            for (int i = 0; i < 4; ++i)
#pragma unroll
                for (int j = 0; j < 4; ++j) mma16816(acc[i][j], ah[i], bh[j]);
            // lo-B fragments, pass 2: hi*lo
#pragma unroll
            for (int j = 0; j < 4; ++j)
                *(uint2*)bl[j] = *(const uint2*)&S[BL_OFF + ((s * 16 + wn * 4 + j) * 32 + lane) * 2];
#pragma unroll
            for (int i = 0; i < 4; ++i)
#pragma unroll
                for (int j = 0; j < 4; ++j) mma16816(acc[i][j], ah[i], bl[j]);
            // lo-A fragments, pass 3: lo*hi
#pragma unroll
            for (int i = 0; i < 4; ++i)
                *(uint4*)al[i] = *(const uint4*)&S[AL_OFF + ((s * 8 + wm * 4 + i) * 32 + lane) * 4];
#pragma unroll
            for (int i = 0; i < 4; ++i)
#pragma unroll
                for (int j = 0; j < 4; ++j) mma16816(acc[i][j], al[i], bh[j]);
        }

        if (it + 1 < NITERS) store_stage(Snxt);
        __syncthreads();
    }

    // epilogue: c-frag direct STG (adjacent col pairs -> float2)
#pragma unroll
    for (int i = 0; i < 4; ++i) {
        int r0 = bm + wm * 64 + i * 16 + (lane >> 2);
#pragma unroll
        for (int j = 0; j < 4; ++j) {
            int c = bn + wn * 32 + j * 8 + (lane & 3) * 2;
            *(float2*)&C[(size_t)r0 * KK + c] = make_float2(acc[i][j][0], acc[i][j][1]);
            *(float2*)&C[(size_t)(r0 + 8) * KK + c] = make_float2(acc[i][j][2], acc[i][j][3]);
        }
    }
}

// ---------------------------------------------------------------------------
// Kernel 2: per-row top-2 argmax + near-tie sequential-fp32 fixup + gather
// Fixup replicates the exact-fp32 kernel's arithmetic bitwise (sequential
// d=0..511 fmaf chain); rows preloaded to smem so the chain is FMA-latency
// bound, not gmem-latency bound.
// ---------------------------------------------------------------------------
__device__ __forceinline__ void merge2(float& v1, int& i1, float& v2, int& i2,
                                       float ov, int oi) {
    if (ov > v1 || (ov == v1 && oi < i1)) {
        v2 = v1; i2 = i1; v1 = ov; i1 = oi;
    } else if (ov > v2 || (ov == v2 && oi < i2)) {
        v2 = ov; i2 = oi;
    }
}

__global__ __launch_bounds__(256)
void argmax_gather_kernel(const float* __restrict__ sims,
                          const float* __restrict__ cb,
                          const float* __restrict__ x,
                          float* __restrict__ preds,
                          void* __restrict__ labels,
                          int labels_are_i64)
{
    const int n = blockIdx.x;
    const int tid = threadIdx.x;
    const float4* row = (const float4*)(sims + (size_t)n * KK);

    float v1 = -CUDART_INF_F, v2 = -CUDART_INF_F;
    int i1 = 0x7FFFFFFF, i2 = 0x7FFFFFFF;
#pragma unroll
    for (int it = 0; it < 2; ++it) {
        int j = tid + it * 256;
        float4 v = row[j];
        int base = j * 4;
        merge2(v1, i1, v2, i2, v.x, base);
        merge2(v1, i1, v2, i2, v.y, base + 1);
        merge2(v1, i1, v2, i2, v.z, base + 2);
        merge2(v1, i1, v2, i2, v.w, base + 3);
    }
#pragma unroll
    for (int off = 16; off > 0; off >>= 1) {
        float ov1 = __shfl_down_sync(0xFFFFFFFFu, v1, off);
        int   oi1 = __shfl_down_sync(0xFFFFFFFFu, i1, off);
        float ov2 = __shfl_down_sync(0xFFFFFFFFu, v2, off);
        int   oi2 = __shfl_down_sync(0xFFFFFFFFu, i2, off);
        merge2(v1, i1, v2, i2, ov1, oi1);
        merge2(v1, i1, v2, i2, ov2, oi2);
    }

    __shared__ float sv1[8], sv2[8];
    __shared__ int   si1[8], si2[8];
    __shared__ float s_exact[2];
    __shared__ int   s_i1, s_i2, s_final, s_fix;
    const int lane = tid & 31, warp = tid >> 5;
    if (lane == 0) { sv1[warp] = v1; si1[warp] = i1; sv2[warp] = v2; si2[warp] = i2; }
    __syncthreads();
    if (tid == 0) {
        float fv1 = sv1[0], fv2 = sv2[0];
        int fi1 = si1[0], fi2 = si2[0];
#pragma unroll
        for (int w = 1; w < 8; ++w) {
            merge2(fv1, fi1, fv2, fi2, sv1[w], si1[w]);
            merge2(fv1, fi1, fv2, fi2, sv2[w], si2[w]);
        }
        s_i1 = fi1; s_i2 = fi2; s_final = fi1;
        // sims error is ~2e-6 RMS (measured); 3e-4 margin = >100 sigma.
        s_fix = (fv1 - fv2 < 3e-4f) ? 1 : 0;
    }
    __syncthreads();

    if (s_fix) {
        __shared__ float sx[DD], sc1[DD], sc2[DD];
        const int a = s_i1, b = s_i2;
        // cooperative preload of the three rows (coalesced)
        for (int d = tid; d < DD; d += 256) {
            sx[d]  = x[(size_t)n * DD + d];
            sc1[d] = cb[(size_t)a * DD + d];
            sc2[d] = cb[(size_t)b * DD + d];
        }
        __syncthreads();
        if (tid < 2) {
            const float* cr = tid ? sc2 : sc1;
            float s = 0.0f;
#pragma unroll 8
            for (int d = 0; d < DD; ++d) s = fmaf(sx[d], cr[d], s);
            s_exact[tid] = s;
        }
        __syncthreads();
        if (tid == 0) {
            const float sA = s_exact[0], sB = s_exact[1];
            int fin;
            if (sA > sB)      fin = a;
            else if (sB > sA) fin = b;
            else              fin = (a < b) ? a : b;
            s_final = fin;
        }
        __syncthreads();
    }

    const int lbl = s_final;
    if (tid == 0) {
        if (labels_are_i64) ((long long*)labels)[n] = (long long)lbl;
        else                ((float*)labels)[n] = (float)lbl;
    }
    if (tid < 128) {
        float4 c = ((const float4*)(cb + (size_t)lbl * DD))[tid];
        ((float4*)(preds + (size_t)n * DD))[tid] = c;
    }
}

// ---------------------------------------------------------------------------
// Launch
// ---------------------------------------------------------------------------
extern "C" void kernel_launch(void* const* d_in, const int* in_sizes, int n_in,
                              void* d_out, int out_size)
{
    const float* x  = (const float*)d_in[0];   // [N, D]
    const float* cb = (const float*)d_in[1];   // [K, D]

    float* out = (float*)d_out;
    const size_t predsSz = (size_t)NN * DD;
    const size_t simsSz  = (size_t)NN * KK;

    size_t labelElems;
    int labels_are_i64;
    if ((size_t)(unsigned)out_size == predsSz + 2 * (size_t)NN + simsSz) {
        labelElems = 2 * (size_t)NN; labels_are_i64 = 1;
    } else {
        labelElems = (size_t)NN;     labels_are_i64 = 0;
    }

    float* preds  = out;
    void*  labels = (void*)(out + predsSz);
    float* sims   = out + predsSz + labelElems;

    static int attr_set = 0;
    if (!attr_set) {
        cudaFuncSetAttribute(gemm_f16x3_kernel,
                             cudaFuncAttributeMaxDynamicSharedMemorySize, SMEM_BYTES);
        attr_set = 1;
    }

    dim3 grid(KK / BN, NN / BM);   // (16, 1024)
    gemm_f16x3_kernel<<<grid, 256, SMEM_BYTES>>>(x, cb, sims);
    argmax_gather_kernel<<<NN, 256>>>(sims, cb, x, preds, labels, labels_are_i64);
}